// round 3
// baseline (speedup 1.0000x reference)
#include <cuda_runtime.h>

// ---------------------------------------------------------------------------
// NeuralODESIR R3: fused RK4 + 4-layer tanh MLP, fp32.
// 64 rows/CTA, 256 threads, 2 CTAs/SM (smem 54KB). W2/W3 via __ldg (L1-hot).
// Packed f32x2 FMA microkernels; XOR-swizzled activation buffers (stride 64).
// ---------------------------------------------------------------------------

typedef unsigned long long ull;

__device__ __forceinline__ ull fma2v(ull a, ull b, ull c) {
    ull d;
    asm("fma.rn.f32x2 %0, %1, %2, %3;" : "=l"(d) : "l"(a), "l"(b), "l"(c));
    return d;
}
__device__ __forceinline__ ull dup2(float x) {
    ull r;
    asm("mov.b64 %0, {%1, %1};" : "=l"(r) : "f"(x));
    return r;
}
__device__ __forceinline__ void unpack2(ull v, float& lo, float& hi) {
    asm("mov.b64 {%0, %1}, %2;" : "=f"(lo), "=f"(hi) : "l"(v));
}

// tanh(x) = 1 - 2/(exp(2x)+1); __expf ~2ulp, safe at +-inf.
__device__ __forceinline__ float tanh_fast(float x) {
    float e = __expf(2.0f * x);
    return 1.0f - __fdividef(2.0f, e + 1.0f);
}

// Swizzles: element (feat c, row r) of a 64-row buffer lives at c*64 + (r ^ rot(c)).
// rot is a multiple of 4 -> preserves float4 blocks; reads in k-loops are broadcast.
__device__ __forceinline__ int rotA(int c) { return (c & 15) << 2; }         // bufA (64 feats)
__device__ __forceinline__ int rotB(int c) { return ((c >> 3) & 15) << 2; }  // bufB (128 feats)

// smem plan (floats)
#define OFF_W1   0
#define OFF_B1   (OFF_W1 + 320)
#define OFF_B2   (OFF_B1 + 64)
#define OFF_B3   (OFF_B2 + 128)
#define OFF_W4   (OFF_B3 + 64)
#define OFF_B4   (OFF_W4 + 192)
#define OFF_TS   (OFF_B4 + 4)
#define OFF_YIN  (OFF_TS + 128)
#define OFF_BUFA (OFF_YIN + 320)
#define OFF_BUFB (OFF_BUFA + 4096)
#define SM_FLOATS (OFF_BUFB + 8192)   // 13508 floats = 54032 B

__global__ void __launch_bounds__(256, 2)
node_sir_kernel(const float* __restrict__ y0, const float* __restrict__ t_span,
                const float* __restrict__ beta, const float* __restrict__ gamma_,
                const float* __restrict__ W1, const float* __restrict__ b1,
                const float* __restrict__ W2, const float* __restrict__ b2,
                const float* __restrict__ W3, const float* __restrict__ b3,
                const float* __restrict__ W4, const float* __restrict__ b4,
                float* __restrict__ out, int B, int T) {
    extern __shared__ float sm[];
    float* W1s  = sm + OFF_W1;
    float* b1s  = sm + OFF_B1;
    float* b2s  = sm + OFF_B2;
    float* b3s  = sm + OFF_B3;
    float* W4s  = sm + OFF_W4;
    float* b4s  = sm + OFF_B4;
    float* tss  = sm + OFF_TS;
    float* yin  = sm + OFF_YIN;   // [5][64]
    float* bufA = sm + OFF_BUFA;  // [64][64] swizzled rotA
    float* bufB = sm + OFF_BUFB;  // [128][64] swizzled rotB

    const int t = threadIdx.x;

    for (int i = t; i < 320; i += 256) W1s[i] = W1[i];
    for (int i = t; i < 64; i += 256) b1s[i] = b1[i];
    for (int i = t; i < 128; i += 256) b2s[i] = b2[i];
    for (int i = t; i < 64; i += 256) b3s[i] = b3[i];
    for (int i = t; i < 192; i += 256) W4s[i] = W4[i];
    if (t < 3) b4s[t] = b4[t];
    for (int i = t; i < T && i < 128; i += 256) tss[i] = t_span[i];

    const int b0  = blockIdx.x * 64;
    const int row = t >> 2;       // 0..63
    const int part = t & 3;       // split-K group for layer 4

    float bS = 0.f, bI = 0.f, bR = 0.f;   // base state (held by part==0 threads)
    float aS = 0.f, aI = 0.f, aR = 0.f;

    if (part == 0) {
        int gr = b0 + row;
        bS = y0[gr * 3 + 0];
        bI = y0[gr * 3 + 1];
        bR = y0[gr * 3 + 2];
        yin[row]           = bS;
        yin[64 + row]      = bI;
        yin[128 + row]     = bR;
        yin[192 + row]     = beta[gr];
        yin[256 + row]     = gamma_[gr];
        float m  = fmaxf(bS, fmaxf(bI, bR));
        float e0 = __expf(bS - m), e1 = __expf(bI - m), e2 = __expf(bR - m);
        float inv = __fdividef(1.0f, e0 + e1 + e2);
        size_t o = (size_t)gr * 3;
        out[o] = e0 * inv; out[o + 1] = e1 * inv; out[o + 2] = e2 * inv;
    }
    __syncthreads();

    // L2 partition: 8 cols x 4 rows per thread. L3: 4 cols x 4 rows.
    const int tx = t & 15;
    const int ty = t >> 4;
    const int r0 = ty << 2;
    const int c0_2 = tx << 3;   // layer-2 col base (N=128)
    const int c0_3 = tx << 2;   // layer-3 col base (N=64)

    for (int s = 0; s < T - 1; ++s) {
        float dt = tss[s + 1] - tss[s];
        for (int sub = 0; sub < 4; ++sub) {
            // ---------- Layer 1: [64,5] @ [5,64] -> bufA ----------
            {
                const int c = t & 63;
                const int rb = (t >> 6) << 4;
                float w0 = W1s[c],        w1 = W1s[64 + c], w2 = W1s[128 + c];
                float w3 = W1s[192 + c],  w4 = W1s[256 + c];
                float bb = b1s[c];
                const int ra = rotA(c);
#pragma unroll
                for (int i = 0; i < 16; ++i) {
                    int r = rb + i;
                    float v = bb;
                    v = fmaf(yin[r],       w0, v);
                    v = fmaf(yin[64 + r],  w1, v);
                    v = fmaf(yin[128 + r], w2, v);
                    v = fmaf(yin[192 + r], w3, v);
                    v = fmaf(yin[256 + r], w4, v);
                    bufA[(c << 6) + (r ^ ra)] = tanh_fast(v);
                }
            }
            __syncthreads();

            // ---------- Layer 2: K=64 -> N=128, bufA -> bufB ----------
            {
                ull acc[8][2];
#pragma unroll
                for (int j = 0; j < 8; ++j) {
                    ull bb = dup2(b2s[c0_2 + j]);
                    acc[j][0] = bb; acc[j][1] = bb;
                }
#pragma unroll 8
                for (int k = 0; k < 64; ++k) {
                    ulonglong2 av = *reinterpret_cast<const ulonglong2*>(
                        bufA + (k << 6) + (r0 ^ rotA(k)));
                    float4 w0 = __ldg(reinterpret_cast<const float4*>(W2 + (k << 7) + c0_2));
                    float4 w1 = __ldg(reinterpret_cast<const float4*>(W2 + (k << 7) + c0_2 + 4));
                    ull d0 = dup2(w0.x), d1 = dup2(w0.y), d2 = dup2(w0.z), d3 = dup2(w0.w);
                    ull d4 = dup2(w1.x), d5 = dup2(w1.y), d6 = dup2(w1.z), d7 = dup2(w1.w);
                    acc[0][0] = fma2v(av.x, d0, acc[0][0]); acc[0][1] = fma2v(av.y, d0, acc[0][1]);
                    acc[1][0] = fma2v(av.x, d1, acc[1][0]); acc[1][1] = fma2v(av.y, d1, acc[1][1]);
                    acc[2][0] = fma2v(av.x, d2, acc[2][0]); acc[2][1] = fma2v(av.y, d2, acc[2][1]);
                    acc[3][0] = fma2v(av.x, d3, acc[3][0]); acc[3][1] = fma2v(av.y, d3, acc[3][1]);
                    acc[4][0] = fma2v(av.x, d4, acc[4][0]); acc[4][1] = fma2v(av.y, d4, acc[4][1]);
                    acc[5][0] = fma2v(av.x, d5, acc[5][0]); acc[5][1] = fma2v(av.y, d5, acc[5][1]);
                    acc[6][0] = fma2v(av.x, d6, acc[6][0]); acc[6][1] = fma2v(av.y, d6, acc[6][1]);
                    acc[7][0] = fma2v(av.x, d7, acc[7][0]); acc[7][1] = fma2v(av.y, d7, acc[7][1]);
                }
                const int roff = r0 ^ (tx << 2);   // rotB(c) == 4*tx for all 8 cols
#pragma unroll
                for (int j = 0; j < 8; ++j) {
                    float x0, x1, x2, x3;
                    unpack2(acc[j][0], x0, x1);
                    unpack2(acc[j][1], x2, x3);
                    *reinterpret_cast<float4*>(bufB + ((c0_2 + j) << 6) + roff) =
                        make_float4(tanh_fast(x0), tanh_fast(x1), tanh_fast(x2), tanh_fast(x3));
                }
            }
            __syncthreads();

            // ---------- Layer 3: K=128 -> N=64, bufB -> bufA ----------
            {
                ull acc[4][2];
#pragma unroll
                for (int j = 0; j < 4; ++j) {
                    ull bb = dup2(b3s[c0_3 + j]);
                    acc[j][0] = bb; acc[j][1] = bb;
                }
#pragma unroll 8
                for (int k = 0; k < 128; ++k) {
                    ulonglong2 av = *reinterpret_cast<const ulonglong2*>(
                        bufB + (k << 6) + (r0 ^ rotB(k)));
                    float4 w = __ldg(reinterpret_cast<const float4*>(W3 + (k << 6) + c0_3));
                    ull d0 = dup2(w.x), d1 = dup2(w.y), d2 = dup2(w.z), d3 = dup2(w.w);
                    acc[0][0] = fma2v(av.x, d0, acc[0][0]); acc[0][1] = fma2v(av.y, d0, acc[0][1]);
                    acc[1][0] = fma2v(av.x, d1, acc[1][0]); acc[1][1] = fma2v(av.y, d1, acc[1][1]);
                    acc[2][0] = fma2v(av.x, d2, acc[2][0]); acc[2][1] = fma2v(av.y, d2, acc[2][1]);
                    acc[3][0] = fma2v(av.x, d3, acc[3][0]); acc[3][1] = fma2v(av.y, d3, acc[3][1]);
                }
#pragma unroll
                for (int j = 0; j < 4; ++j) {
                    int c = c0_3 + j;
                    float x0, x1, x2, x3;
                    unpack2(acc[j][0], x0, x1);
                    unpack2(acc[j][1], x2, x3);
                    *reinterpret_cast<float4*>(bufA + (c << 6) + (r0 ^ rotA(c))) =
                        make_float4(tanh_fast(x0), tanh_fast(x1), tanh_fast(x2), tanh_fast(x3));
                }
            }
            __syncthreads();

            // ---------- Layer 4 (split-K over 4 threads/row) + RK4 ----------
            {
                float s0 = 0.f, s1 = 0.f, s2 = 0.f;
                const int kb = part << 4;
#pragma unroll
                for (int i = 0; i < 16; ++i) {
                    int k = kb + ((i + (part << 2)) & 15);   // phase-stagger: no bank conflict
                    float h = bufA[(k << 6) + (row ^ rotA(k))];
                    s0 = fmaf(h, W4s[k * 3 + 0], s0);
                    s1 = fmaf(h, W4s[k * 3 + 1], s1);
                    s2 = fmaf(h, W4s[k * 3 + 2], s2);
                }
                s0 += __shfl_xor_sync(0xffffffffu, s0, 1);
                s1 += __shfl_xor_sync(0xffffffffu, s1, 1);
                s2 += __shfl_xor_sync(0xffffffffu, s2, 1);
                s0 += __shfl_xor_sync(0xffffffffu, s0, 2);
                s1 += __shfl_xor_sync(0xffffffffu, s1, 2);
                s2 += __shfl_xor_sync(0xffffffffu, s2, 2);

                if (part == 0) {
                    s0 += b4s[0]; s1 += b4s[1]; s2 += b4s[2];
                    if (sub == 0) {
                        aS = s0; aI = s1; aR = s2;
                    } else if (sub == 3) {
                        aS += s0; aI += s1; aR += s2;
                    } else {
                        aS = fmaf(2.0f, s0, aS);
                        aI = fmaf(2.0f, s1, aI);
                        aR = fmaf(2.0f, s2, aR);
                    }
                    if (sub < 3) {
                        float cy = (sub == 2) ? dt : 0.5f * dt;
                        yin[row]       = fmaf(cy, s0, bS);
                        yin[64 + row]  = fmaf(cy, s1, bI);
                        yin[128 + row] = fmaf(cy, s2, bR);
                    } else {
                        float c = dt * (1.0f / 6.0f);
                        bS = fmaf(c, aS, bS);
                        bI = fmaf(c, aI, bI);
                        bR = fmaf(c, aR, bR);
                        yin[row]       = bS;
                        yin[64 + row]  = bI;
                        yin[128 + row] = bR;
                        float m  = fmaxf(bS, fmaxf(bI, bR));
                        float e0 = __expf(bS - m), e1 = __expf(bI - m), e2 = __expf(bR - m);
                        float inv = __fdividef(1.0f, e0 + e1 + e2);
                        size_t o = ((size_t)(s + 1) * B + (b0 + row)) * 3;
                        out[o] = e0 * inv; out[o + 1] = e1 * inv; out[o + 2] = e2 * inv;
                    }
                }
            }
            __syncthreads();
        }
    }
}

extern "C" void kernel_launch(void* const* d_in, const int* in_sizes, int n_in,
                              void* d_out, int out_size) {
    const float* y0 = (const float*)d_in[0];
    const float* ts = (const float*)d_in[1];
    const float* be = (const float*)d_in[2];
    const float* ga = (const float*)d_in[3];
    const float* W1 = (const float*)d_in[4];
    const float* b1 = (const float*)d_in[5];
    const float* W2 = (const float*)d_in[6];
    const float* b2 = (const float*)d_in[7];
    const float* W3 = (const float*)d_in[8];
    const float* b3 = (const float*)d_in[9];
    const float* W4 = (const float*)d_in[10];
    const float* b4 = (const float*)d_in[11];

    int B = in_sizes[2];  // beta length
    int T = in_sizes[1];  // t_span length

    size_t smem_bytes = (size_t)SM_FLOATS * sizeof(float);
    cudaFuncSetAttribute(node_sir_kernel,
                         cudaFuncAttributeMaxDynamicSharedMemorySize,
                         (int)smem_bytes);

    node_sir_kernel<<<B / 64, 256, smem_bytes>>>(
        y0, ts, be, ga, W1, b1, W2, b2, W3, b3, W4, b4,
        (float*)d_out, B, T);
}

// round 4
// speedup vs baseline: 1.1857x; 1.1857x over previous
#include <cuda_runtime.h>

// ---------------------------------------------------------------------------
// NeuralODESIR R4: fused RK4 + 4-layer tanh MLP, fp32.
// 128 rows/CTA, 256 threads, 1 CTA/SM. All weights in smem.
// Warp-per-16-cols, lane-per-4-rows register tiles (64 out/thread).
// Weights read as broadcast LDS (f32x2 packed over column pairs) -> ~0.3 B/MAC.
// ---------------------------------------------------------------------------

typedef unsigned long long ull;

__device__ __forceinline__ ull fma2v(ull a, ull b, ull c) {
    ull d;
    asm("fma.rn.f32x2 %0, %1, %2, %3;" : "=l"(d) : "l"(a), "l"(b), "l"(c));
    return d;
}
__device__ __forceinline__ ull dup2(float x) {
    ull r;
    asm("mov.b64 %0, {%1, %1};" : "=l"(r) : "f"(x));
    return r;
}
__device__ __forceinline__ void unpack2(ull v, float& lo, float& hi) {
    asm("mov.b64 {%0, %1}, %2;" : "=f"(lo), "=f"(hi) : "l"(v));
}

// tanh(x) = 1 - 2/(exp(2x)+1); __expf ~2ulp, correct at +-large x.
__device__ __forceinline__ float tanh_fast(float x) {
    float e = __expf(2.0f * x);
    return 1.0f - __fdividef(2.0f, e + 1.0f);
}

// smem plan (floats)
#define OFF_W1   0
#define OFF_B1   (OFF_W1 + 320)
#define OFF_W2   (OFF_B1 + 64)
#define OFF_B2   (OFF_W2 + 8192)
#define OFF_W3   (OFF_B2 + 128)
#define OFF_B3   (OFF_W3 + 8192)
#define OFF_W4   (OFF_B3 + 64)
#define OFF_B4   (OFF_W4 + 192)
#define OFF_TS   (OFF_B4 + 4)
#define OFF_YIN  (OFF_TS + 128)
#define OFF_BUFA (OFF_YIN + 640)            // [64 feats][128 rows]
#define OFF_BUFB (OFF_BUFA + 64 * 128)      // [128 feats][128 rows]
#define SM_FLOATS (OFF_BUFB + 128 * 128)    // 42500 floats = 170000 B

__global__ void __launch_bounds__(256, 1)
node_sir_kernel(const float* __restrict__ y0, const float* __restrict__ t_span,
                const float* __restrict__ beta, const float* __restrict__ gamma_,
                const float* __restrict__ W1, const float* __restrict__ b1,
                const float* __restrict__ W2, const float* __restrict__ b2,
                const float* __restrict__ W3, const float* __restrict__ b3,
                const float* __restrict__ W4, const float* __restrict__ b4,
                float* __restrict__ out, int B, int T) {
    extern __shared__ float sm[];
    float* W1s  = sm + OFF_W1;
    float* b1s  = sm + OFF_B1;
    float* W2s  = sm + OFF_W2;
    float* b2s  = sm + OFF_B2;
    float* W3s  = sm + OFF_W3;
    float* b3s  = sm + OFF_B3;
    float* W4s  = sm + OFF_W4;
    float* b4s  = sm + OFF_B4;
    float* tss  = sm + OFF_TS;
    float* yin  = sm + OFF_YIN;   // [5][128]
    float* bufA = sm + OFF_BUFA;  // [64][128]
    float* bufB = sm + OFF_BUFB;  // [128][128]

    const int t    = threadIdx.x;
    const int lane = t & 31;
    const int warp = t >> 5;

    for (int i = t; i < 320; i += 256) W1s[i] = W1[i];
    for (int i = t; i < 64; i += 256) b1s[i] = b1[i];
    for (int i = t; i < 8192; i += 256) W2s[i] = W2[i];
    for (int i = t; i < 128; i += 256) b2s[i] = b2[i];
    for (int i = t; i < 8192; i += 256) W3s[i] = W3[i];
    for (int i = t; i < 64; i += 256) b3s[i] = b3[i];
    for (int i = t; i < 192; i += 256) W4s[i] = W4[i];
    if (t < 3) b4s[t] = b4[t];
    for (int i = t; i < T && i < 128; i += 256) tss[i] = t_span[i];

    const int b0   = blockIdx.x << 7;
    const int row4 = t >> 1;   // layer-4: row per thread pair
    const int part = t & 1;    // layer-4: split-K half

    float bS = 0.f, bI = 0.f, bR = 0.f;
    float aS = 0.f, aI = 0.f, aR = 0.f;

    if (part == 0) {
        int gr = b0 + row4;
        bS = y0[gr * 3 + 0];
        bI = y0[gr * 3 + 1];
        bR = y0[gr * 3 + 2];
        yin[row4]        = bS;
        yin[128 + row4]  = bI;
        yin[256 + row4]  = bR;
        yin[384 + row4]  = beta[gr];
        yin[512 + row4]  = gamma_[gr];
        float m  = fmaxf(bS, fmaxf(bI, bR));
        float e0 = __expf(bS - m), e1 = __expf(bI - m), e2 = __expf(bR - m);
        float inv = __fdividef(1.0f, e0 + e1 + e2);
        size_t o = (size_t)gr * 3;
        out[o] = e0 * inv; out[o + 1] = e1 * inv; out[o + 2] = e2 * inv;
    }
    __syncthreads();

    const int c0_2 = warp << 4;   // layer-2: 16 cols per warp (N=128)
    const int c0_3 = warp << 3;   // layer-3: 8 cols per warp  (N=64)
    const int r4   = lane << 2;   // 4 rows per lane

    for (int s = 0; s < T - 1; ++s) {
        float dt = tss[s + 1] - tss[s];
        for (int sub = 0; sub < 4; ++sub) {
            // ---------- Layer 1: [128,5] @ [5,64] -> bufA[64][128] ----------
            {
                const int r  = t & 127;
                const int cb = (t >> 7) << 5;   // 32 cols per thread
                float v0 = yin[r],       v1 = yin[128 + r], v2 = yin[256 + r];
                float v3 = yin[384 + r], v4 = yin[512 + r];
#pragma unroll 8
                for (int j = 0; j < 32; ++j) {
                    int c = cb + j;
                    float v = b1s[c];                 // broadcast
                    v = fmaf(v0, W1s[c],        v);
                    v = fmaf(v1, W1s[64 + c],   v);
                    v = fmaf(v2, W1s[128 + c],  v);
                    v = fmaf(v3, W1s[192 + c],  v);
                    v = fmaf(v4, W1s[256 + c],  v);
                    bufA[(c << 7) + r] = tanh_fast(v);
                }
            }
            __syncthreads();

            // ---------- Layer 2: K=64 -> N=128, bufA -> bufB ----------
            {
                ull acc[4][8];
#pragma unroll
                for (int jp = 0; jp < 8; ++jp) {
                    ull bb = *reinterpret_cast<const ull*>(b2s + c0_2 + 2 * jp);
                    acc[0][jp] = bb; acc[1][jp] = bb; acc[2][jp] = bb; acc[3][jp] = bb;
                }
#pragma unroll 4
                for (int k = 0; k < 64; ++k) {
                    float4 a = *reinterpret_cast<const float4*>(bufA + (k << 7) + r4);
                    ull ad0 = dup2(a.x), ad1 = dup2(a.y), ad2 = dup2(a.z), ad3 = dup2(a.w);
                    const ulonglong2* wp =
                        reinterpret_cast<const ulonglong2*>(W2s + (k << 7) + c0_2);
                    ulonglong2 wv0 = wp[0], wv1 = wp[1], wv2 = wp[2], wv3 = wp[3];
                    ull w[8] = {wv0.x, wv0.y, wv1.x, wv1.y, wv2.x, wv2.y, wv3.x, wv3.y};
#pragma unroll
                    for (int jp = 0; jp < 8; ++jp) {
                        acc[0][jp] = fma2v(ad0, w[jp], acc[0][jp]);
                        acc[1][jp] = fma2v(ad1, w[jp], acc[1][jp]);
                        acc[2][jp] = fma2v(ad2, w[jp], acc[2][jp]);
                        acc[3][jp] = fma2v(ad3, w[jp], acc[3][jp]);
                    }
                }
#pragma unroll
                for (int jp = 0; jp < 8; ++jp) {
                    float x0l, x0h, x1l, x1h, x2l, x2h, x3l, x3h;
                    unpack2(acc[0][jp], x0l, x0h);
                    unpack2(acc[1][jp], x1l, x1h);
                    unpack2(acc[2][jp], x2l, x2h);
                    unpack2(acc[3][jp], x3l, x3h);
                    int c = c0_2 + 2 * jp;
                    *reinterpret_cast<float4*>(bufB + (c << 7) + r4) =
                        make_float4(tanh_fast(x0l), tanh_fast(x1l),
                                    tanh_fast(x2l), tanh_fast(x3l));
                    *reinterpret_cast<float4*>(bufB + ((c + 1) << 7) + r4) =
                        make_float4(tanh_fast(x0h), tanh_fast(x1h),
                                    tanh_fast(x2h), tanh_fast(x3h));
                }
            }
            __syncthreads();

            // ---------- Layer 3: K=128 -> N=64, bufB -> bufA ----------
            {
                ull acc[4][4];
#pragma unroll
                for (int jp = 0; jp < 4; ++jp) {
                    ull bb = *reinterpret_cast<const ull*>(b3s + c0_3 + 2 * jp);
                    acc[0][jp] = bb; acc[1][jp] = bb; acc[2][jp] = bb; acc[3][jp] = bb;
                }
#pragma unroll 4
                for (int k = 0; k < 128; ++k) {
                    float4 a = *reinterpret_cast<const float4*>(bufB + (k << 7) + r4);
                    ull ad0 = dup2(a.x), ad1 = dup2(a.y), ad2 = dup2(a.z), ad3 = dup2(a.w);
                    const ulonglong2* wp =
                        reinterpret_cast<const ulonglong2*>(W3s + (k << 6) + c0_3);
                    ulonglong2 wv0 = wp[0], wv1 = wp[1];
                    ull w[4] = {wv0.x, wv0.y, wv1.x, wv1.y};
#pragma unroll
                    for (int jp = 0; jp < 4; ++jp) {
                        acc[0][jp] = fma2v(ad0, w[jp], acc[0][jp]);
                        acc[1][jp] = fma2v(ad1, w[jp], acc[1][jp]);
                        acc[2][jp] = fma2v(ad2, w[jp], acc[2][jp]);
                        acc[3][jp] = fma2v(ad3, w[jp], acc[3][jp]);
                    }
                }
#pragma unroll
                for (int jp = 0; jp < 4; ++jp) {
                    float x0l, x0h, x1l, x1h, x2l, x2h, x3l, x3h;
                    unpack2(acc[0][jp], x0l, x0h);
                    unpack2(acc[1][jp], x1l, x1h);
                    unpack2(acc[2][jp], x2l, x2h);
                    unpack2(acc[3][jp], x3l, x3h);
                    int c = c0_3 + 2 * jp;
                    *reinterpret_cast<float4*>(bufA + (c << 7) + r4) =
                        make_float4(tanh_fast(x0l), tanh_fast(x1l),
                                    tanh_fast(x2l), tanh_fast(x3l));
                    *reinterpret_cast<float4*>(bufA + ((c + 1) << 7) + r4) =
                        make_float4(tanh_fast(x0h), tanh_fast(x1h),
                                    tanh_fast(x2h), tanh_fast(x3h));
                }
            }
            __syncthreads();

            // ---------- Layer 4 (split-K over 2 threads/row) + RK4 ----------
            {
                float s0 = 0.f, s1 = 0.f, s2 = 0.f;
                const int kb = part << 5;
#pragma unroll 8
                for (int i = 0; i < 32; ++i) {
                    int k = kb + i;
                    float h = bufA[(k << 7) + row4];
                    s0 = fmaf(h, W4s[k * 3 + 0], s0);
                    s1 = fmaf(h, W4s[k * 3 + 1], s1);
                    s2 = fmaf(h, W4s[k * 3 + 2], s2);
                }
                s0 += __shfl_xor_sync(0xffffffffu, s0, 1);
                s1 += __shfl_xor_sync(0xffffffffu, s1, 1);
                s2 += __shfl_xor_sync(0xffffffffu, s2, 1);

                if (part == 0) {
                    s0 += b4s[0]; s1 += b4s[1]; s2 += b4s[2];
                    if (sub == 0) {
                        aS = s0; aI = s1; aR = s2;
                    } else if (sub == 3) {
                        aS += s0; aI += s1; aR += s2;
                    } else {
                        aS = fmaf(2.0f, s0, aS);
                        aI = fmaf(2.0f, s1, aI);
                        aR = fmaf(2.0f, s2, aR);
                    }
                    if (sub < 3) {
                        float cy = (sub == 2) ? dt : 0.5f * dt;
                        yin[row4]        = fmaf(cy, s0, bS);
                        yin[128 + row4]  = fmaf(cy, s1, bI);
                        yin[256 + row4]  = fmaf(cy, s2, bR);
                    } else {
                        float c = dt * (1.0f / 6.0f);
                        bS = fmaf(c, aS, bS);
                        bI = fmaf(c, aI, bI);
                        bR = fmaf(c, aR, bR);
                        yin[row4]        = bS;
                        yin[128 + row4]  = bI;
                        yin[256 + row4]  = bR;
                        float m  = fmaxf(bS, fmaxf(bI, bR));
                        float e0 = __expf(bS - m), e1 = __expf(bI - m), e2 = __expf(bR - m);
                        float inv = __fdividef(1.0f, e0 + e1 + e2);
                        size_t o = ((size_t)(s + 1) * B + (b0 + row4)) * 3;
                        out[o] = e0 * inv; out[o + 1] = e1 * inv; out[o + 2] = e2 * inv;
                    }
                }
            }
            __syncthreads();
        }
    }
}

extern "C" void kernel_launch(void* const* d_in, const int* in_sizes, int n_in,
                              void* d_out, int out_size) {
    const float* y0 = (const float*)d_in[0];
    const float* ts = (const float*)d_in[1];
    const float* be = (const float*)d_in[2];
    const float* ga = (const float*)d_in[3];
    const float* W1 = (const float*)d_in[4];
    const float* b1 = (const float*)d_in[5];
    const float* W2 = (const float*)d_in[6];
    const float* b2 = (const float*)d_in[7];
    const float* W3 = (const float*)d_in[8];
    const float* b3 = (const float*)d_in[9];
    const float* W4 = (const float*)d_in[10];
    const float* b4 = (const float*)d_in[11];

    int B = in_sizes[2];  // beta length
    int T = in_sizes[1];  // t_span length

    size_t smem_bytes = (size_t)SM_FLOATS * sizeof(float);
    cudaFuncSetAttribute(node_sir_kernel,
                         cudaFuncAttributeMaxDynamicSharedMemorySize,
                         (int)smem_bytes);

    node_sir_kernel<<<B / 128, 256, smem_bytes>>>(
        y0, ts, be, ga, W1, b1, W2, b2, W3, b3, W4, b4,
        (float*)d_out, B, T);
}